// round 6
// baseline (speedup 1.0000x reference)
#include <cuda_runtime.h>
#include <cub/cub.cuh>

// Problem constants (fixed by the reference setup_inputs)
constexpr int B  = 64;
constexpr int H  = 512;
constexpr int W  = 512;
constexpr int HW = H * W;        // 262144 = 2^18
constexpr int N  = B * HW;       // 16777216

// Batch-partition/decode stage constants
constexpr int THREADS = 256;
constexpr int TILE    = 4096;
constexpr int ITEMS   = TILE / THREADS;  // 16
constexpr int NB      = N / TILE;        // 4096

// Custom onesweep constants: 3 passes x 10 bits over key bits [0,30)
// (keys have bits 30..31 == 01 constant since scores are in [0,1))
constexpr int RS_THREADS = 512;
constexpr int RS_ITEMS   = 16;
constexpr int RS_TILE    = RS_THREADS * RS_ITEMS;  // 8192
constexpr int RS_NT      = N / RS_TILE;            // 2048
constexpr int RBITS      = 10;
constexpr int RBINS      = 1 << RBITS;             // 1024
constexpr unsigned FLAG_A  = 1u << 30;   // tile aggregate ready
constexpr unsigned FLAG_P  = 2u << 30;   // inclusive prefix ready
constexpr unsigned VALMASK = (1u << 30) - 1u;

// Static scratch (no allocation allowed)
__device__ unsigned g_keys_a[N];
__device__ unsigned g_keys_b[N];
__device__ unsigned g_vals_a[N];
__device__ unsigned g_vals_b[N];
__device__ float2   g_pairs[N];
__device__ unsigned g_bhist[64 * NB];
__device__ unsigned g_boff[64 * NB];
__device__ unsigned g_lookback[3][RS_NT * RBINS];  // 24MB, zeroed per launch
__device__ unsigned g_dhist[3 * RBINS];
__device__ unsigned g_dbase[3 * RBINS];
__device__ unsigned g_ticket[4];

// ---------------------------------------------------------------------------
// Kernel 1: 8-neighbor NMS + key encode + offset-pair interleave.
// ---------------------------------------------------------------------------
__global__ void nms_encode_kernel(const float* __restrict__ hm,
                                  const float* __restrict__ off,
                                  unsigned* __restrict__ keys,
                                  unsigned* __restrict__ vals,
                                  float2* __restrict__ pairs) {
    int g = blockIdx.x * blockDim.x + threadIdx.x;
    if (g >= N) return;
    int idx = g & (HW - 1);
    int b   = g >> 18;
    int y   = idx >> 9;
    int x   = idx & (W - 1);

    const float* img = hm + (size_t)b * HW;
    float v = __ldg(img + idx);

    float m = -__int_as_float(0x7f800000);  // -inf
    if (y > 0) {
        const float* r = img + (y - 1) * W + x;
        if (x > 0)      m = fmaxf(m, __ldg(r - 1));
        m = fmaxf(m, __ldg(r));
        if (x < W - 1)  m = fmaxf(m, __ldg(r + 1));
    }
    {
        const float* r = img + y * W + x;
        if (x > 0)      m = fmaxf(m, __ldg(r - 1));
        if (x < W - 1)  m = fmaxf(m, __ldg(r + 1));
    }
    if (y < H - 1) {
        const float* r = img + (y + 1) * W + x;
        if (x > 0)      m = fmaxf(m, __ldg(r - 1));
        m = fmaxf(m, __ldg(r));
        if (x < W - 1)  m = fmaxf(m, __ldg(r + 1));
    }

    float jv = (m >= v) ? 0.6f * v : v;

    unsigned u = __float_as_uint(jv);
    unsigned e = u ^ (((unsigned)((int)u >> 31)) | 0x80000000u);
    keys[g] = ~e;
    vals[g] = (unsigned)g;

    const float* ob = off + (size_t)b * 2 * HW;
    float xo = __ldg(ob + idx);        // channel 0: x-offset
    float yo = __ldg(ob + HW + idx);   // channel 1: y-offset
    pairs[g] = make_float2(xo, yo);
}

// ---------------------------------------------------------------------------
// Kernel 2: global histograms for all 3 digit places (1024 bins each).
// ---------------------------------------------------------------------------
__global__ void key_hist_kernel(const unsigned* __restrict__ keys,
                                unsigned* __restrict__ dhist) {
    __shared__ unsigned h[3 * RBINS];
    int t = threadIdx.x;
    for (int i = t; i < 3 * RBINS; i += blockDim.x) h[i] = 0;
    __syncthreads();

    const uint4* k4 = (const uint4*)keys;
    int total4 = N / 4;
    for (int i = blockIdx.x * blockDim.x + t; i < total4;
         i += gridDim.x * blockDim.x) {
        uint4 q = k4[i];
        unsigned kk[4] = {q.x, q.y, q.z, q.w};
#pragma unroll
        for (int j = 0; j < 4; j++) {
            atomicAdd(&h[kk[j] & (RBINS - 1)], 1u);
            atomicAdd(&h[RBINS + ((kk[j] >> 10) & (RBINS - 1))], 1u);
            atomicAdd(&h[2 * RBINS + ((kk[j] >> 20) & (RBINS - 1))], 1u);
        }
    }
    __syncthreads();
    for (int i = t; i < 3 * RBINS; i += blockDim.x)
        if (h[i]) atomicAdd(&dhist[i], h[i]);
}

// ---------------------------------------------------------------------------
// Kernel 3: exclusive scan of each 1024-bin histogram -> digit bases.
// ---------------------------------------------------------------------------
__global__ void base_scan_kernel(const unsigned* __restrict__ dhist,
                                 unsigned* __restrict__ dbase) {
    typedef cub::BlockScan<unsigned, RBINS> BS;
    __shared__ typename BS::TempStorage ts;
    int p = blockIdx.x;
    unsigned v = dhist[p * RBINS + threadIdx.x], r;
    BS(ts).ExclusiveSum(v, r);
    dbase[p * RBINS + threadIdx.x] = r;
}

// ---------------------------------------------------------------------------
// Kernel 4: one onesweep pass (10-bit digit at `shift`), stable, pairs.
// ---------------------------------------------------------------------------
__global__ void __launch_bounds__(RS_THREADS, 2)
onesweep_pass_kernel(const unsigned* __restrict__ kin,
                     const unsigned* __restrict__ vin,
                     unsigned* __restrict__ kout,
                     unsigned* __restrict__ vout,
                     const unsigned* __restrict__ dbase,
                     unsigned* lookback,
                     unsigned* ticket,
                     int shift) {
    __shared__ union {
        unsigned short cnt[16 * RBINS];   // [warp][digit] counts -> prefixes
        unsigned stage[RS_TILE];          // aliased staging (32KB)
    } sm;
    __shared__ unsigned sh_adj[RBINS];
    __shared__ unsigned short sh_P[RBINS];
    __shared__ unsigned sh_tile;
    typedef cub::BlockScan<int, RS_THREADS> BS;
    __shared__ typename BS::TempStorage scan_ts;

    int t = threadIdx.x, warp = t >> 5, lane = t & 31;
    unsigned ltmask = (1u << lane) - 1u;

    if (t == 0) sh_tile = atomicAdd(ticket, 1u);
    for (int i = t; i < 16 * RBINS / 2; i += RS_THREADS)
        ((unsigned*)sm.cnt)[i] = 0;
    __syncthreads();
    unsigned tile = sh_tile;

    // warp-striped: element(warp, i, lane) = tile*RS_TILE + warp*512 + i*32 + lane
    size_t base = (size_t)tile * RS_TILE + warp * 512 + lane;

    unsigned key[RS_ITEMS];
#pragma unroll
    for (int i = 0; i < RS_ITEMS; i++) key[i] = kin[base + i * 32];

    // Stable warp ranking in memory order (item-major, then lane)
    unsigned short rwi[RS_ITEMS];
#pragma unroll
    for (int i = 0; i < RS_ITEMS; i++) {
        unsigned d = (key[i] >> shift) & (RBINS - 1);
        unsigned mmask = __match_any_sync(0xFFFFFFFFu, d);
        unsigned before = sm.cnt[warp * RBINS + d];
        rwi[i] = (unsigned short)(before + __popc(mmask & ltmask));
        if ((mmask & ltmask) == 0)  // lowest lane in group is leader
            sm.cnt[warp * RBINS + d] = (unsigned short)(before + __popc(mmask));
        __syncwarp();
    }
    __syncthreads();

    // Phase B: thread t owns digits 2t, 2t+1. Warp-exclusive prefixes in
    // place, tile totals in regs. Publish aggregates immediately.
    int d0 = 2 * t, d1 = 2 * t + 1;
    int T0 = 0, T1 = 0;
    {
        int run = 0;
#pragma unroll
        for (int w = 0; w < 16; w++) {
            int c = sm.cnt[w * RBINS + d0];
            sm.cnt[w * RBINS + d0] = (unsigned short)run;
            run += c;
        }
        T0 = run;
        run = 0;
#pragma unroll
        for (int w = 0; w < 16; w++) {
            int c = sm.cnt[w * RBINS + d1];
            sm.cnt[w * RBINS + d1] = (unsigned short)run;
            run += c;
        }
        T1 = run;
    }
    unsigned flag0 = (tile == 0) ? FLAG_P : FLAG_A;
    atomicExch(&lookback[(size_t)tile * RBINS + d0], flag0 | (unsigned)T0);
    atomicExch(&lookback[(size_t)tile * RBINS + d1], flag0 | (unsigned)T1);

    // In-tile exclusive digit prefix P[d]
    {
        int items[2] = {T0, T1}, px[2];
        BS(scan_ts).ExclusiveSum(items, px);
        sh_P[d0] = (unsigned short)px[0];
        sh_P[d1] = (unsigned short)px[1];

        // Decoupled lookback -> exclusive cross-tile prefix E
        unsigned E0 = 0, E1 = 0;
        if (tile > 0) {
            int tt = (int)tile - 1;
            while (true) {
                unsigned s = *(volatile const unsigned*)
                    (lookback + (size_t)tt * RBINS + d0);
                if (s & FLAG_P) { E0 += s & VALMASK; break; }
                if (s & FLAG_A) { E0 += s & VALMASK; tt--; }
            }
            tt = (int)tile - 1;
            while (true) {
                unsigned s = *(volatile const unsigned*)
                    (lookback + (size_t)tt * RBINS + d1);
                if (s & FLAG_P) { E1 += s & VALMASK; break; }
                if (s & FLAG_A) { E1 += s & VALMASK; tt--; }
            }
            atomicExch(&lookback[(size_t)tile * RBINS + d0],
                       FLAG_P | (E0 + (unsigned)T0));
            atomicExch(&lookback[(size_t)tile * RBINS + d1],
                       FLAG_P | (E1 + (unsigned)T1));
        }
        // pos = dbase[d] + E[d] + (s - P[d])  ->  sh_adj[d] + s
        sh_adj[d0] = dbase[d0] + E0 - (unsigned)px[0];
        sh_adj[d1] = dbase[d1] + E1 - (unsigned)px[1];
    }
    __syncthreads();

    // In-tile slot (= stable sorted position within tile)
    unsigned slot[RS_ITEMS];
#pragma unroll
    for (int i = 0; i < RS_ITEMS; i++) {
        unsigned d = (key[i] >> shift) & (RBINS - 1);
        slot[i] = (unsigned)sh_P[d] + (unsigned)sm.cnt[warp * RBINS + d]
                + (unsigned)rwi[i];
    }
    __syncthreads();  // done with cnt -> alias as staging

    // Stage keys by slot; emit coalesced; remember pos per slot
#pragma unroll
    for (int i = 0; i < RS_ITEMS; i++) sm.stage[slot[i]] = key[i];
    __syncthreads();
    unsigned pos[RS_ITEMS];
#pragma unroll
    for (int j = 0; j < RS_ITEMS; j++) {
        int s = t + j * RS_THREADS;
        unsigned k = sm.stage[s];
        unsigned d = (k >> shift) & (RBINS - 1);
        unsigned p = sh_adj[d] + (unsigned)s;
        kout[p] = k;
        pos[j] = p;
    }
    __syncthreads();

    // Stage values by slot; emit to the same positions
#pragma unroll
    for (int i = 0; i < RS_ITEMS; i++) sm.stage[slot[i]] = vin[base + i * 32];
    __syncthreads();
#pragma unroll
    for (int j = 0; j < RS_ITEMS; j++) {
        int s = t + j * RS_THREADS;
        vout[pos[j]] = sm.stage[s];
    }
}

// ---------------------------------------------------------------------------
// Kernel 5: per-block 64-bin batch histogram over the score-sorted values.
// ---------------------------------------------------------------------------
__global__ void hist_kernel(const unsigned* __restrict__ vs,
                            unsigned* __restrict__ bh) {
    __shared__ unsigned cnt[64];
    int t = threadIdx.x;
    if (t < 64) cnt[t] = 0;
    __syncthreads();
    const uint4* v4 = (const uint4*)(vs + (size_t)blockIdx.x * TILE);
    for (int i = t; i < TILE / 4; i += THREADS) {
        uint4 q = v4[i];
        atomicAdd(&cnt[q.x >> 18], 1u);
        atomicAdd(&cnt[q.y >> 18], 1u);
        atomicAdd(&cnt[q.z >> 18], 1u);
        atomicAdd(&cnt[q.w >> 18], 1u);
    }
    __syncthreads();
    if (t < 64) bh[(size_t)t * NB + blockIdx.x] = cnt[t];
}

// ---------------------------------------------------------------------------
// Kernel 6: exclusive scan of per-block counts (one batch per block) + b*HW.
// ---------------------------------------------------------------------------
__global__ void scan_kernel(const unsigned* __restrict__ bh,
                            unsigned* __restrict__ bo) {
    typedef cub::BlockScan<unsigned, 1024> BS;
    __shared__ typename BS::TempStorage ts;
    int b = blockIdx.x;
    const unsigned* src = bh + (size_t)b * NB;
    unsigned* dst = bo + (size_t)b * NB;
    unsigned v[4];
#pragma unroll
    for (int i = 0; i < 4; i++) v[i] = src[threadIdx.x * 4 + i];
    BS(ts).ExclusiveSum(v, v);
    unsigned base = (unsigned)b * (unsigned)HW;
#pragma unroll
    for (int i = 0; i < 4; i++) dst[threadIdx.x * 4 + i] = v[i] + base;
}

// ---------------------------------------------------------------------------
// Kernel 7: fused stable 64-way partition + decode with SMEM staging.
// ---------------------------------------------------------------------------
typedef cub::BlockRadixRank<THREADS, 6, false> BRR;

struct BatchExtractor {
    __device__ __forceinline__ unsigned Digit(unsigned key) const {
        return key >> 18;
    }
};

__global__ void scatter_decode_kernel(const unsigned* __restrict__ vs,
                                      const unsigned* __restrict__ ds,
                                      const unsigned* __restrict__ bo,
                                      const float2* __restrict__ pairs,
                                      float* __restrict__ out) {
    __shared__ union SM {
        typename BRR::TempStorage rank;
        struct { unsigned v[TILE]; unsigned d[TILE]; } ex;
        __device__ SM() {}
    } sm;
    __shared__ unsigned sh_base[64];

    int t = threadIdx.x;
    size_t base = (size_t)blockIdx.x * TILE + (size_t)t * ITEMS;

    unsigned v[ITEMS], d[ITEMS];
    const uint4* v4 = (const uint4*)(vs + base);
    const uint4* d4 = (const uint4*)(ds + base);
#pragma unroll
    for (int j = 0; j < ITEMS / 4; j++) {
        uint4 q = v4[j];
        v[4 * j + 0] = q.x; v[4 * j + 1] = q.y;
        v[4 * j + 2] = q.z; v[4 * j + 3] = q.w;
        uint4 p = d4[j];
        d[4 * j + 0] = p.x; d[4 * j + 1] = p.y;
        d[4 * j + 2] = p.z; d[4 * j + 3] = p.w;
    }

    int ranks[ITEMS];
    int exc[BRR::BINS_TRACKED_PER_THREAD];
    BatchExtractor ext;
    BRR(sm.rank).RankKeys(v, ranks, ext, exc);

    if (t < 64)
        sh_base[t] = bo[(size_t)t * NB + blockIdx.x] - (unsigned)exc[0];
    __syncthreads();

#pragma unroll
    for (int i = 0; i < ITEMS; i++) sm.ex.v[ranks[i]] = v[i];
#pragma unroll
    for (int i = 0; i < ITEMS; i++) sm.ex.d[ranks[i]] = d[i];
    __syncthreads();

#pragma unroll
    for (int k = 0; k < ITEMS; k++) {
        int s = t + k * THREADS;
        unsigned vv = sm.ex.v[s];
        unsigned dd = sm.ex.d[s];
        unsigned b   = vv >> 18;
        unsigned idx = vv & 0x3FFFFu;
        unsigned pos = sh_base[b] + (unsigned)s;

        unsigned e = ~dd;
        unsigned msk = (e & 0x80000000u) ? 0x80000000u : 0xFFFFFFFFu;
        float score = __uint_as_float(e ^ msk);
        int y = idx >> 9, x = idx & (W - 1);

        float2 p = __ldg(&pairs[((size_t)b << 18) | idx]);

        float* o = out + (size_t)pos * 3;
        o[0] = (float)y + p.y + 0.5f;   // p.y = y-offset
        o[1] = (float)x + p.x + 0.5f;   // p.x = x-offset
        o[2] = score;
    }
}

extern "C" void kernel_launch(void* const* d_in, const int* in_sizes, int n_in,
                              void* d_out, int out_size) {
    const float* hm  = (const float*)d_in[0];
    const float* off = (const float*)d_in[1];
    float* out = (float*)d_out;

    unsigned *ka, *kb, *va, *vb, *bh, *bo, *lb, *dh, *db, *tk;
    float2* pr;
    cudaGetSymbolAddress((void**)&ka, g_keys_a);
    cudaGetSymbolAddress((void**)&kb, g_keys_b);
    cudaGetSymbolAddress((void**)&va, g_vals_a);
    cudaGetSymbolAddress((void**)&vb, g_vals_b);
    cudaGetSymbolAddress((void**)&bh, g_bhist);
    cudaGetSymbolAddress((void**)&bo, g_boff);
    cudaGetSymbolAddress((void**)&lb, g_lookback);
    cudaGetSymbolAddress((void**)&dh, g_dhist);
    cudaGetSymbolAddress((void**)&db, g_dbase);
    cudaGetSymbolAddress((void**)&tk, g_ticket);
    cudaGetSymbolAddress((void**)&pr, g_pairs);

    // Re-zero per-launch state (graph-replay safe)
    cudaMemsetAsync(lb, 0, sizeof(g_lookback), 0);
    cudaMemsetAsync(dh, 0, sizeof(g_dhist), 0);
    cudaMemsetAsync(tk, 0, sizeof(g_ticket), 0);

    const int blocks = (N + THREADS - 1) / THREADS;
    nms_encode_kernel<<<blocks, THREADS>>>(hm, off, ka, va, pr);

    key_hist_kernel<<<296, 256>>>(ka, dh);
    base_scan_kernel<<<3, RBINS>>>(dh, db);

    // 3 x 10-bit onesweep passes: a->b->a->b
    onesweep_pass_kernel<<<RS_NT, RS_THREADS>>>(
        ka, va, kb, vb, db + 0 * RBINS, lb + 0 * (size_t)RS_NT * RBINS,
        tk + 0, 0);
    onesweep_pass_kernel<<<RS_NT, RS_THREADS>>>(
        kb, vb, ka, va, db + 1 * RBINS, lb + 1 * (size_t)RS_NT * RBINS,
        tk + 1, 10);
    onesweep_pass_kernel<<<RS_NT, RS_THREADS>>>(
        ka, va, kb, vb, db + 2 * RBINS, lb + 2 * (size_t)RS_NT * RBINS,
        tk + 2, 20);

    hist_kernel<<<NB, THREADS>>>(vb, bh);
    scan_kernel<<<64, 1024>>>(bh, bo);
    scatter_decode_kernel<<<NB, THREADS>>>(vb, kb, bo, pr, out);
}